// round 1
// baseline (speedup 1.0000x reference)
#include <cuda_runtime.h>
#include <math.h>

#define N_PTS   1000000
#define NSEG    64
#define HID     128
#define AFFD    16
#define AH      64
#define AL      32
#define AA      8

#define TPB     256
#define PPT     4
#define PTS_PER_CTA (TPB * PPT)

#define ACC_STRIDE (AFFD + 2)   // 16 aff sums, err sum, count

// Global scratch accumulator (no allocations allowed)
__device__ float g_accum[NSEG * ACC_STRIDE];

__global__ void zero_accum_kernel() {
    int i = blockIdx.x * blockDim.x + threadIdx.x;
    if (i < NSEG * ACC_STRIDE) g_accum[i] = 0.0f;
}

__global__ __launch_bounds__(TPB) void point_kernel(
    const float* __restrict__ pos, const int* __restrict__ batch,
    const float* __restrict__ Wf1, const float* __restrict__ bf1,
    const float* __restrict__ Wf2, const float* __restrict__ bf2,
    const float* __restrict__ Wg1, const float* __restrict__ bg1,
    const float* __restrict__ Wg2, const float* __restrict__ bg2,
    float* __restrict__ out_aff, float* __restrict__ out_recon,
    float* __restrict__ out_cspatial)
{
    __shared__ float sWf1[3 * HID];
    __shared__ float sbf1[HID];
    __shared__ float sWf2[HID * AFFD];
    __shared__ float sbf2[AFFD];
    __shared__ float sWg1[AFFD * HID];
    __shared__ float sbg1[HID];
    __shared__ float sWg2[HID * 3];
    __shared__ float sbg2[3];
    __shared__ float sacc[NSEG * ACC_STRIDE];

    for (int i = threadIdx.x; i < 3 * HID; i += TPB)       sWf1[i] = Wf1[i];
    for (int i = threadIdx.x; i < HID; i += TPB)           sbf1[i] = bf1[i];
    for (int i = threadIdx.x; i < HID * AFFD; i += TPB)    sWf2[i] = Wf2[i];
    for (int i = threadIdx.x; i < AFFD; i += TPB)          sbf2[i] = bf2[i];
    for (int i = threadIdx.x; i < AFFD * HID; i += TPB)    sWg1[i] = Wg1[i];
    for (int i = threadIdx.x; i < HID; i += TPB)           sbg1[i] = bg1[i];
    for (int i = threadIdx.x; i < HID * 3; i += TPB)       sWg2[i] = Wg2[i];
    for (int i = threadIdx.x; i < 3; i += TPB)             sbg2[i] = bg2[i];
    for (int i = threadIdx.x; i < NSEG * ACC_STRIDE; i += TPB) sacc[i] = 0.0f;
    __syncthreads();

    const int base = blockIdx.x * PTS_PER_CTA + threadIdx.x;

    float px[PPT], py[PPT], pz[PPT];
    float aff[PPT][AFFD];
    int   seg[PPT];
    bool  valid[PPT];

    #pragma unroll
    for (int i = 0; i < PPT; i++) {
        int p = base + i * TPB;
        valid[i] = (p < N_PTS);
        int pp = valid[i] ? p : (N_PTS - 1);
        px[i] = pos[pp * 3 + 0];
        py[i] = pos[pp * 3 + 1];
        pz[i] = pos[pp * 3 + 2];
        seg[i] = batch[pp];
        #pragma unroll
        for (int k = 0; k < AFFD; k++) aff[i][k] = sbf2[k];
    }

    // ---- F: affordances = relu(pos@Wf1 + bf1) @ Wf2 + bf2 ----
    for (int j = 0; j < HID; j++) {
        float w0 = sWf1[j], w1 = sWf1[HID + j], w2 = sWf1[2 * HID + j];
        float b  = sbf1[j];
        float h[PPT];
        #pragma unroll
        for (int i = 0; i < PPT; i++) {
            float v = fmaf(px[i], w0, fmaf(py[i], w1, fmaf(pz[i], w2, b)));
            h[i] = fmaxf(v, 0.0f);
        }
        const float* wrow = &sWf2[j * AFFD];
        #pragma unroll
        for (int k = 0; k < AFFD; k++) {
            float wk = wrow[k];
            #pragma unroll
            for (int i = 0; i < PPT; i++) aff[i][k] = fmaf(h[i], wk, aff[i][k]);
        }
    }

    // store affordances (vectorized: 16 floats = 4x float4, 16B aligned)
    #pragma unroll
    for (int i = 0; i < PPT; i++) {
        if (valid[i]) {
            int p = base + i * TPB;
            float4* dst = (float4*)(out_aff + (size_t)p * AFFD);
            #pragma unroll
            for (int q = 0; q < 4; q++) {
                dst[q] = make_float4(aff[i][4*q], aff[i][4*q+1], aff[i][4*q+2], aff[i][4*q+3]);
            }
        }
    }

    // ---- G: recon = relu(aff@Wg1 + bg1) @ Wg2 + bg2 ----
    float rx[PPT], ry[PPT], rz[PPT];
    #pragma unroll
    for (int i = 0; i < PPT; i++) { rx[i] = sbg2[0]; ry[i] = sbg2[1]; rz[i] = sbg2[2]; }

    for (int j = 0; j < HID; j++) {
        float g[PPT];
        float bj = sbg1[j];
        #pragma unroll
        for (int i = 0; i < PPT; i++) g[i] = bj;
        #pragma unroll
        for (int k = 0; k < AFFD; k++) {
            float wk = sWg1[k * HID + j];
            #pragma unroll
            for (int i = 0; i < PPT; i++) g[i] = fmaf(aff[i][k], wk, g[i]);
        }
        float u0 = sWg2[j * 3 + 0], u1 = sWg2[j * 3 + 1], u2 = sWg2[j * 3 + 2];
        #pragma unroll
        for (int i = 0; i < PPT; i++) {
            float gi = fmaxf(g[i], 0.0f);
            rx[i] = fmaf(gi, u0, rx[i]);
            ry[i] = fmaf(gi, u1, ry[i]);
            rz[i] = fmaf(gi, u2, rz[i]);
        }
    }

    float err[PPT];
    #pragma unroll
    for (int i = 0; i < PPT; i++) {
        float dx = px[i] - rx[i], dy = py[i] - ry[i], dz = pz[i] - rz[i];
        err[i] = fmaf(dx, dx, fmaf(dy, dy, dz * dz));
        if (valid[i]) {
            int p = base + i * TPB;
            out_recon[(size_t)p * 3 + 0] = rx[i];
            out_recon[(size_t)p * 3 + 1] = ry[i];
            out_recon[(size_t)p * 3 + 2] = rz[i];
            out_cspatial[p] = err[i];
        }
    }

    // ---- segment reduction (batch is sorted; warp-uniform fast path) ----
    const unsigned FULL = 0xffffffffu;
    #pragma unroll
    for (int i = 0; i < PPT; i++) {
        int sg = seg[i];
        float cnt = valid[i] ? 1.0f : 0.0f;
        float e   = valid[i] ? err[i] : 0.0f;
        float av[AFFD];
        #pragma unroll
        for (int k = 0; k < AFFD; k++) av[k] = valid[i] ? aff[i][k] : 0.0f;

        int sg0 = __shfl_sync(FULL, sg, 0);
        bool uniform = __all_sync(FULL, sg == sg0);
        if (uniform) {
            #pragma unroll
            for (int off = 16; off >= 1; off >>= 1) {
                cnt += __shfl_xor_sync(FULL, cnt, off);
                e   += __shfl_xor_sync(FULL, e,   off);
                #pragma unroll
                for (int k = 0; k < AFFD; k++)
                    av[k] += __shfl_xor_sync(FULL, av[k], off);
            }
            if ((threadIdx.x & 31) == 0) {
                float* a = &sacc[sg * ACC_STRIDE];
                #pragma unroll
                for (int k = 0; k < AFFD; k++) atomicAdd(&a[k], av[k]);
                atomicAdd(&a[AFFD], e);
                atomicAdd(&a[AFFD + 1], cnt);
            }
        } else {
            if (valid[i]) {
                float* a = &sacc[sg * ACC_STRIDE];
                #pragma unroll
                for (int k = 0; k < AFFD; k++) atomicAdd(&a[k], av[k]);
                atomicAdd(&a[AFFD], e);
                atomicAdd(&a[AFFD + 1], 1.0f);
            }
        }
    }
    __syncthreads();

    // flush only the CTA's segment range to global (batch sorted)
    int first = blockIdx.x * PTS_PER_CTA;
    int last  = min(first + PTS_PER_CTA - 1, N_PTS - 1);
    int smin = batch[first];
    int smax = batch[last];
    int total = (smax - smin + 1) * ACC_STRIDE;
    for (int t = threadIdx.x; t < total; t += TPB) {
        float v = sacc[smin * ACC_STRIDE + t];
        if (v != 0.0f) atomicAdd(&g_accum[smin * ACC_STRIDE + t], v);
    }
}

__device__ __forceinline__ float sigmoidf_(float x) {
    return 1.0f / (1.0f + expf(-x));
}

__global__ void agent_kernel(
    const float* __restrict__ agent_h,
    const float* __restrict__ Wx, const float* __restrict__ Wh,
    const float* __restrict__ bx, const float* __restrict__ bh,
    const float* __restrict__ Wlat, const float* __restrict__ blat,
    const float* __restrict__ Wact, const float* __restrict__ bact,
    float* __restrict__ out_csig, float* __restrict__ out_action,
    float* __restrict__ out_hnext)
{
    int b = blockIdx.x;
    int u = threadIdx.x;   // 0..63
    __shared__ float s_aff[AFFD];
    __shared__ float s_h[AH];
    __shared__ float s_hn[AH];
    __shared__ float s_lat[AL];

    float cnt = g_accum[b * ACC_STRIDE + AFFD + 1];
    float denom = fmaxf(cnt, 1.0f);
    if (u < AFFD) s_aff[u] = g_accum[b * ACC_STRIDE + u] / denom;
    if (u == 0)   out_csig[b] = g_accum[b * ACC_STRIDE + AFFD] / denom;
    s_h[u] = agent_h[b * AH + u];
    __syncthreads();

    float gxr = bx[u], gxz = bx[AH + u], gxn = bx[2 * AH + u];
    #pragma unroll
    for (int k = 0; k < AFFD; k++) {
        float a = s_aff[k];
        gxr = fmaf(a, Wx[k * 3 * AH + u], gxr);
        gxz = fmaf(a, Wx[k * 3 * AH + AH + u], gxz);
        gxn = fmaf(a, Wx[k * 3 * AH + 2 * AH + u], gxn);
    }
    float ghr = bh[u], ghz = bh[AH + u], ghn = bh[2 * AH + u];
    #pragma unroll
    for (int k = 0; k < AH; k++) {
        float hh = s_h[k];
        ghr = fmaf(hh, Wh[k * 3 * AH + u], ghr);
        ghz = fmaf(hh, Wh[k * 3 * AH + AH + u], ghz);
        ghn = fmaf(hh, Wh[k * 3 * AH + 2 * AH + u], ghn);
    }
    float r = sigmoidf_(gxr + ghr);
    float z = sigmoidf_(gxz + ghz);
    float n = tanhf(gxn + r * ghn);
    float hn = (1.0f - z) * n + z * s_h[u];
    out_hnext[b * AH + u] = hn;
    s_hn[u] = hn;
    __syncthreads();

    if (u < AL) {
        float acc = blat[u];
        #pragma unroll
        for (int k = 0; k < AH; k++) acc = fmaf(s_hn[k], Wlat[k * AL + u], acc);
        s_lat[u] = tanhf(acc);
    }
    __syncthreads();

    if (u < AA) {
        float acc = bact[u];
        #pragma unroll
        for (int k = 0; k < AL; k++) acc = fmaf(s_lat[k], Wact[k * AA + u], acc);
        out_action[b * AA + u] = acc;
    }
}

extern "C" void kernel_launch(void* const* d_in, const int* in_sizes, int n_in,
                              void* d_out, int out_size) {
    const float* pos   = (const float*)d_in[0];
    const int*   batch = (const int*)d_in[1];
    const float* agent_h = (const float*)d_in[2];
    // d_in[3] coherence_signal_prev, d_in[4] coherence_spatial_prev: unused
    const float* Wf1 = (const float*)d_in[5];
    const float* bf1 = (const float*)d_in[6];
    const float* Wf2 = (const float*)d_in[7];
    const float* bf2 = (const float*)d_in[8];
    const float* Wg1 = (const float*)d_in[9];
    const float* bg1 = (const float*)d_in[10];
    const float* Wg2 = (const float*)d_in[11];
    const float* bg2 = (const float*)d_in[12];
    const float* Wx  = (const float*)d_in[13];
    const float* Wh  = (const float*)d_in[14];
    const float* bx  = (const float*)d_in[15];
    const float* bh  = (const float*)d_in[16];
    const float* Wlat = (const float*)d_in[17];
    const float* blat = (const float*)d_in[18];
    const float* Wact = (const float*)d_in[19];
    const float* bact = (const float*)d_in[20];

    float* out = (float*)d_out;
    // Output layout: tuple flattened in order
    float* out_aff      = out;                                    // N*16
    float* out_recon    = out + (size_t)N_PTS * AFFD;             // N*3
    float* out_csig     = out + (size_t)N_PTS * 19;               // B
    float* out_cspatial = out + (size_t)N_PTS * 19 + NSEG;        // N
    float* out_action   = out + (size_t)N_PTS * 20 + NSEG;        // B*8
    float* out_hnext    = out + (size_t)N_PTS * 20 + NSEG + NSEG * AA; // B*64

    zero_accum_kernel<<<(NSEG * ACC_STRIDE + 255) / 256, 256>>>();

    int grid = (N_PTS + PTS_PER_CTA - 1) / PTS_PER_CTA;
    point_kernel<<<grid, TPB>>>(pos, batch,
                                Wf1, bf1, Wf2, bf2, Wg1, bg1, Wg2, bg2,
                                out_aff, out_recon, out_cspatial);

    agent_kernel<<<NSEG, AH>>>(agent_h, Wx, Wh, bx, bh, Wlat, blat, Wact, bact,
                               out_csig, out_action, out_hnext);
}